// round 16
// baseline (speedup 1.0000x reference)
#include <cuda_runtime.h>
#include <cuda_bf16.h>
#include <math.h>

#define BATCH 1024
#define MBUF  16384
#define DIM   512
#define NCLS  100
#define NLRN  50
#define NBINS 4096
#define NBLK  592          // 4 per SM x 148 SMs; guaranteed single wave

// ---------------- scratch (__device__ globals; no allocation) ----------------
__device__ __align__(16) __nv_bfloat16 g_fn16[BATCH * DIM];
__device__ __align__(16) float         g_fn32[BATCH * DIM];
__device__ __align__(16) __nv_bfloat16 g_bfn16[(size_t)MBUF * DIM];
__device__ unsigned char               g_blu8[MBUF];
__device__ __align__(16) float         g_scratch[(size_t)BATCH * MBUF];  // fallback sims
__device__ __align__(16) unsigned      g_histg[(size_t)BATCH * NBINS];   // fallback hist
__device__ __align__(16) float         g_candg[(size_t)BATCH * NBINS];   // fallback cand
__device__ int   g_clist[(size_t)NCLS * MBUF];   // buffer indices per class
__device__ int   g_ccnt[NCLS];                   // zero-init; reset by final
__device__ float g_Sc[NCLS * DIM];               // per-class buffer vec sums
__device__ float g_Stot[DIM];                    // atomic-accumulated; reset by final
__device__ float g_scores[BATCH];
__device__ float g_row_loss[BATCH];
__device__ int   g_row_valid[BATCH];
__device__ float g_row_kl[BATCH];
__device__ float g_bl[NCLS];
__device__ int   g_vc[NCLS];
__device__ int   g_sync1;                        // stage-A grid barrier; reset by final
__device__ int   g_scdone;                       // sc publish counter; reset by final
__device__ int   g_done;                         // completion counter; reset by final
__device__ __align__(16) float g_op[NLRN * DIM];
__device__ __align__(16) float g_np[NLRN * DIM];

__device__ __forceinline__ float clip10(float x) { return fminf(fmaxf(x, -10.f), 10.f); }

__device__ __forceinline__ int bin_of(float s) {
    int b = (int)(__fmul_rn(__fadd_rn(s, 10.f), 204.8f));
    return max(0, min(NBINS - 1, b));
}

// ================= ONE PERSISTENT KERNEL =====================================
__global__ void __launch_bounds__(256, 4) k_all(const float* __restrict__ f,
                                                const float* __restrict__ bf,
                                                const float* __restrict__ W,
                                                const float* __restrict__ b,
                                                const int* __restrict__ labels,
                                                const int* __restrict__ blab,
                                                const float* __restrict__ protos,
                                                const float* __restrict__ oldp,
                                                const int* __restrict__ lc,
                                                float* __restrict__ out) {
    __shared__ __align__(16) char SM[22528];
    __shared__ int sT, sAbove, sNc, sNfail, sLast;
    __shared__ int sfail[4];
    float* rf  = (float*)(SM + 16384);   // 1 KB
    float* rg  = (float*)(SM + 17408);   // 1 KB
    int*   ri  = (int*)(SM + 18432);     // 1 KB
    int*   suf = (int*)(SM + 19456);     // 1 KB
    float* sf  = (float*)(SM + 20480);   // 2 KB (512 floats)

    int bid = blockIdx.x, t = threadIdx.x;
    int w = t >> 5, l = t & 31;
    int gw = bid * 8 + w;                // global warp id, [0, 4736)

    // ================= STAGE A ==============================================
    // buffer rows: pairs p -> rows 2p, 2p+1 ; grid-stride over 8192 pairs
#pragma unroll 1
    for (int p = gw; p < MBUF / 2; p += NBLK * 8) {
        int r0 = 2 * p;
        float4 v[4], u[4];
        float ss0 = 0.f, ss1 = 0.f;
#pragma unroll
        for (int j = 0; j < 4; j++) {
            int d = j * 128 + l * 4;
            v[j] = *(const float4*)(bf + (size_t)r0 * DIM + d);
            u[j] = *(const float4*)(bf + (size_t)(r0 + 1) * DIM + d);
            ss0 += v[j].x * v[j].x + v[j].y * v[j].y + v[j].z * v[j].z + v[j].w * v[j].w;
            ss1 += u[j].x * u[j].x + u[j].y * u[j].y + u[j].z * u[j].z + u[j].w * u[j].w;
        }
#pragma unroll
        for (int o = 16; o > 0; o >>= 1) {
            ss0 += __shfl_xor_sync(0xffffffffu, ss0, o);
            ss1 += __shfl_xor_sync(0xffffffffu, ss1, o);
        }
        float i0 = 1.f / fmaxf(sqrtf(ss0), 1e-12f);
        float i1 = 1.f / fmaxf(sqrtf(ss1), 1e-12f);
#pragma unroll
        for (int j = 0; j < 4; j++) {
            int d = j * 128 + l * 4;
            __nv_bfloat162* o0 = (__nv_bfloat162*)(g_bfn16 + (size_t)r0 * DIM + d);
            o0[0] = __floats2bfloat162_rn(v[j].x * i0, v[j].y * i0);
            o0[1] = __floats2bfloat162_rn(v[j].z * i0, v[j].w * i0);
            __nv_bfloat162* o1 = (__nv_bfloat162*)(g_bfn16 + (size_t)(r0 + 1) * DIM + d);
            o1[0] = __floats2bfloat162_rn(u[j].x * i1, u[j].y * i1);
            o1[1] = __floats2bfloat162_rn(u[j].z * i1, u[j].w * i1);
        }
        if (l == 0) {
            int lab0 = blab[r0], lab1 = blab[r0 + 1];
            g_blu8[r0] = (unsigned char)lab0;
            g_blu8[r0 + 1] = (unsigned char)lab1;
            int s0 = atomicAdd(&g_ccnt[lab0], 1);   // order affects branch-only sums
            g_clist[(size_t)lab0 * MBUF + s0] = r0;
            int s1 = atomicAdd(&g_ccnt[lab1], 1);
            g_clist[(size_t)lab1 * MBUF + s1] = r0 + 1;
        }
    }
    // feature rows on warps gw in [3712, 4736): row = gw - 3712
    if (gw >= 3712) {
        int r = gw - 3712;
        float4 v[4];
        float ss = 0.f, dw = 0.f;
#pragma unroll
        for (int j = 0; j < 4; j++) {
            int d = j * 128 + l * 4;
            v[j] = *(const float4*)(f + r * DIM + d);
            float4 w4 = *(const float4*)(W + d);
            ss += v[j].x * v[j].x + v[j].y * v[j].y + v[j].z * v[j].z + v[j].w * v[j].w;
            dw += v[j].x * w4.x + v[j].y * w4.y + v[j].z * w4.z + v[j].w * w4.w;
        }
#pragma unroll
        for (int o = 16; o > 0; o >>= 1) {
            ss += __shfl_xor_sync(0xffffffffu, ss, o);
            dw += __shfl_xor_sync(0xffffffffu, dw, o);
        }
        float inv = 1.f / fmaxf(sqrtf(ss), 1e-12f);
        if (l == 0) g_scores[r] = 1.f / (1.f + expf(-(dw + b[0])));
#pragma unroll
        for (int j = 0; j < 4; j++) {
            int d = j * 128 + l * 4;
            float4 n;
            n.x = v[j].x * inv; n.y = v[j].y * inv; n.z = v[j].z * inv; n.w = v[j].w * inv;
            *(float4*)(g_fn32 + r * DIM + d) = n;
            __nv_bfloat162* o16 = (__nv_bfloat162*)(g_fn16 + r * DIM + d);
            o16[0] = __floats2bfloat162_rn(n.x, n.y);
            o16[1] = __floats2bfloat162_rn(n.z, n.w);
        }
    }
    // protos on blocks [492, 592)
    if (bid >= 492) {
        int i = bid - 492;
        int j = (i < NLRN) ? i : i - NLRN;
        const float* src = ((i < NLRN) ? oldp : protos) + (size_t)lc[j] * DIM;
        float* dst = ((i < NLRN) ? g_op : g_np) + (size_t)j * DIM;
        float v0 = src[t], v1 = src[t + 256];
        float ss = v0 * v0 + v1 * v1;
        rf[t] = ss; __syncthreads();
        for (int s = 128; s > 0; s >>= 1) {
            if (t < s) rf[t] += rf[t + s];
            __syncthreads();
        }
        float inv = 1.f / fmaxf(sqrtf(rf[0]), 1e-12f);
        dst[t] = v0 * inv;
        dst[t + 256] = v1 * inv;
    }

    // ---------------- grid barrier (all blocks resident -> safe) ------------
    __threadfence();
    __syncthreads();
    if (t == 0) {
        atomicAdd(&g_sync1, 1);
        while (*(volatile int*)&g_sync1 < NBLK) __nanosleep(32);
    }
    __syncthreads();
    __threadfence();

    // ================= STAGE B ==============================================
    if (bid < 100) {
        // ---- S_c gather + Stot accumulate + publish ----
        int c = bid;
        int cntb = g_ccnt[c];
        const int* blist = g_clist + (size_t)c * MBUF;
        float ax = 0.f, ay = 0.f;
        int i = 0;
#pragma unroll 1
        for (; i + 4 <= cntb; i += 4) {
            unsigned x0 = ((const unsigned*)(g_bfn16 + (size_t)blist[i]     * DIM))[t];
            unsigned x1 = ((const unsigned*)(g_bfn16 + (size_t)blist[i + 1] * DIM))[t];
            unsigned x2 = ((const unsigned*)(g_bfn16 + (size_t)blist[i + 2] * DIM))[t];
            unsigned x3 = ((const unsigned*)(g_bfn16 + (size_t)blist[i + 3] * DIM))[t];
            float2 p0 = __bfloat1622float2(*(__nv_bfloat162*)&x0);
            float2 p1 = __bfloat1622float2(*(__nv_bfloat162*)&x1);
            float2 p2 = __bfloat1622float2(*(__nv_bfloat162*)&x2);
            float2 p3 = __bfloat1622float2(*(__nv_bfloat162*)&x3);
            ax += (p0.x + p1.x) + (p2.x + p3.x);
            ay += (p0.y + p1.y) + (p2.y + p3.y);
        }
        for (; i < cntb; i++) {
            unsigned x0 = ((const unsigned*)(g_bfn16 + (size_t)blist[i] * DIM))[t];
            float2 p0 = __bfloat1622float2(*(__nv_bfloat162*)&x0);
            ax += p0.x; ay += p0.y;
        }
        g_Sc[c * DIM + 2 * t]     = ax;
        g_Sc[c * DIM + 2 * t + 1] = ay;
        atomicAdd(&g_Stot[2 * t],     ax);    // branch-only; order ok
        atomicAdd(&g_Stot[2 * t + 1], ay);
        __threadfence();
        __syncthreads();
        if (t == 0) atomicAdd(&g_scdone, 1);
    } else if (bid < 200) {
        // ---- boundary loss per class (direct label scan) ----
        int c = bid - 100;
        float s1a = 0, s2a = 0, s1b = 0, s2b = 0, ssum = 0;
        int cnt = 0;
#pragma unroll 1
        for (int r = 0; r < BATCH; r++) {
            if (labels[r] == c) {
                float va = f[r * DIM + t], vb = f[r * DIM + t + 256];
                s1a += va; s2a += va * va;
                s1b += vb; s2b += vb * vb;
                cnt++;
                if (t == 0) ssum += g_scores[r];
            }
        }
        float n = (float)cnt, safen = fmaxf(n, 1.f), denv = fmaxf(n - 1.f, 1.f);
        float ma = s1a / safen, mb = s1b / safen;
        float va = (s2a - n * ma * ma) / denv, vb = (s2b - n * mb * mb) / denv;
        rf[t] = va + vb; __syncthreads();
        for (int s = 128; s > 0; s >>= 1) {
            if (t < s) rf[t] += rf[t + s];
            __syncthreads();
        }
        if (t == 0) {
            float var_mean = fminf(fmaxf(rf[0] / 512.f, 1e-6f), 100.f);
            float target = 1.f / (1.f + expf(-var_mean));
            float mean_s = ssum / safen;
            float d = mean_s - target;
            float bl = fminf(fmaxf(d * d, 0.f), 2.f);
            g_bl[c] = (cnt > 1) ? bl : 0.f;
            g_vc[c] = (cnt > 1) ? 1 : 0;
        }
    } else if (bid < 328) {
        // ---- PRD KL divergence, 8 rows per block ----
        int base = (bid - 200) * 8;
        float (*sfr)[DIM] = (float (*)[DIM])SM;            // 16 KB
        float (*so)[64] = (float (*)[64])(SM + 16384);     // 2 KB
        float (*sn)[64] = (float (*)[64])(SM + 18432);     // 2 KB
        for (int i = t; i < 8 * DIM / 4; i += 256) {
            ((float4*)&sfr[0][0])[i] = ((const float4*)(g_fn32 + (size_t)base * DIM))[i];
        }
        __syncthreads();
        for (int j = w; j < NLRN; j += 8) {
            float po_r[16], pn_r[16];
#pragma unroll
            for (int q = 0; q < 16; q++) {
                po_r[q] = g_op[j * DIM + l + 32 * q];
                pn_r[q] = g_np[j * DIM + l + 32 * q];
            }
#pragma unroll
            for (int r = 0; r < 8; r++) {
                float ao = 0.f, an = 0.f;
#pragma unroll
                for (int q = 0; q < 16; q++) {
                    float x = sfr[r][l + 32 * q];
                    ao += x * po_r[q];
                    an += x * pn_r[q];
                }
#pragma unroll
                for (int o = 16; o > 0; o >>= 1) {
                    ao += __shfl_xor_sync(0xffffffffu, ao, o);
                    an += __shfl_xor_sync(0xffffffffu, an, o);
                }
                if (l == 0) { so[r][j] = clip10(ao * 5.f); sn[r][j] = clip10(an * 5.f); }
            }
        }
        __syncthreads();
        {
            int r = w;
            float a1 = (l < NLRN) ? so[r][l] : -1e30f;
            float a2 = (l + 32 < NLRN) ? so[r][l + 32] : -1e30f;
            float b1 = (l < NLRN) ? sn[r][l] : -1e30f;
            float b2 = (l + 32 < NLRN) ? sn[r][l + 32] : -1e30f;
            float mo = fmaxf(a1, a2), mn = fmaxf(b1, b2);
#pragma unroll
            for (int o = 16; o > 0; o >>= 1) {
                mo = fmaxf(mo, __shfl_xor_sync(0xffffffffu, mo, o));
                mn = fmaxf(mn, __shfl_xor_sync(0xffffffffu, mn, o));
            }
            float eo = ((l < NLRN) ? __expf(a1 - mo) : 0.f) + ((l + 32 < NLRN) ? __expf(a2 - mo) : 0.f);
            float en = ((l < NLRN) ? __expf(b1 - mn) : 0.f) + ((l + 32 < NLRN) ? __expf(b2 - mn) : 0.f);
#pragma unroll
            for (int o = 16; o > 0; o >>= 1) {
                eo += __shfl_xor_sync(0xffffffffu, eo, o);
                en += __shfl_xor_sync(0xffffffffu, en, o);
            }
            float lZo = logf(eo), lZn = logf(en);
            float klp = 0.f;
            if (l < NLRN) {
                float p = __expf(a1 - mo) / eo;
                klp += p * ((a1 - mo - lZo) - (b1 - mn - lZn));
            }
            if (l + 32 < NLRN) {
                float p = __expf(a2 - mo) / eo;
                klp += p * ((a2 - mo - lZo) - (b2 - mn - lZn));
            }
#pragma unroll
            for (int o = 16; o > 0; o >>= 1) klp += __shfl_xor_sync(0xffffffffu, klp, o);
            if (l == 0) g_row_kl[base + r] = klp;
        }
    } else {
        // ---- pos (4 rows/block, 2 warps/row) + spin + bound + fallback ----
        int rbase = (bid - 328) * 4;
        int j = w & 3, slot = w >> 2;
        int row = rbase + j;
        bool haveRow = (row < BATCH);
        float es = 0.f;
        int lab = 0, cnt = 0;
        if (haveRow) {
            lab = labels[row];
            cnt = g_ccnt[lab];
            const int* list = g_clist + (size_t)lab * MBUF;
            const uint4* fp = (const uint4*)(g_fn16 + (size_t)row * DIM);
            uint4 rx0 = fp[2 * l], rx1 = fp[2 * l + 1];
            float2 frv[8];
#pragma unroll
            for (int q = 0; q < 4; q++) {
                frv[q]     = __bfloat1622float2(((const __nv_bfloat162*)&rx0)[q]);
                frv[q + 4] = __bfloat1622float2(((const __nv_bfloat162*)&rx1)[q]);
            }
#pragma unroll 1
            for (int i = 2 * slot; i < cnt; i += 4) {
                int v0 = list[i];
                bool has2 = (i + 1 < cnt);
                int v1 = has2 ? list[i + 1] : v0;
                const uint4* p0 = (const uint4*)(g_bfn16 + (size_t)v0 * DIM) + 2 * l;
                const uint4* p1 = (const uint4*)(g_bfn16 + (size_t)v1 * DIM) + 2 * l;
                uint4 a0 = p0[0], a1 = p0[1];
                uint4 b0 = p1[0], b1 = p1[1];
                float d0 = 0.f, d1 = 0.f;
#pragma unroll
                for (int q = 0; q < 4; q++) {
                    float2 x0 = __bfloat1622float2(((const __nv_bfloat162*)&a0)[q]);
                    float2 x1 = __bfloat1622float2(((const __nv_bfloat162*)&a1)[q]);
                    d0 += frv[q].x * x0.x + frv[q].y * x0.y;
                    d0 += frv[q + 4].x * x1.x + frv[q + 4].y * x1.y;
                    float2 y0 = __bfloat1622float2(((const __nv_bfloat162*)&b0)[q]);
                    float2 y1 = __bfloat1622float2(((const __nv_bfloat162*)&b1)[q]);
                    d1 += frv[q].x * y0.x + frv[q].y * y0.y;
                    d1 += frv[q + 4].x * y1.x + frv[q + 4].y * y1.y;
                }
#pragma unroll
                for (int o = 16; o > 0; o >>= 1) {
                    d0 += __shfl_xor_sync(0xffffffffu, d0, o);
                    d1 += __shfl_xor_sync(0xffffffffu, d1, o);
                }
                if (l == 0) {
                    es += __expf(d0 * 5.f);
                    if (has2) es += __expf(d1 * 5.f);
                }
            }
        }
        if (l == 0) rg[w] = es;                    // rg[0..7]: per-warp partials
        if (t == 0) sNfail = 0;
        __syncthreads();

        // ---- wait for all 100 sc blocks (all resident -> no deadlock) ----
        if (t == 0) {
            while (*(volatile int*)&g_scdone < 100) __nanosleep(64);
        }
        __syncthreads();
        __threadfence();

        // ---- bound check: warp jj (<4) handles row rbase+jj ----
        if (w < 4) {
            int row2 = rbase + w;
            if (row2 < BATCH) {
                int lab2 = labels[row2];
                int cnt2 = g_ccnt[lab2];
                const float* frow = g_fn32 + (size_t)row2 * DIM;
                const float* Sc = g_Sc + lab2 * DIM;
                float d1 = 0.f, d2 = 0.f;
#pragma unroll
                for (int q = 0; q < 16; q++) {
                    float x = frow[l + 32 * q];
                    d1 += x * g_Stot[l + 32 * q];
                    d2 += x * Sc[l + 32 * q];
                }
#pragma unroll
                for (int o = 16; o > 0; o >>= 1) {
                    d1 += __shfl_xor_sync(0xffffffffu, d1, o);
                    d2 += __shfl_xor_sync(0xffffffffu, d2, o);
                }
                if (l == 0) {
                    float pose = rg[w] + rg[w + 4];
                    int n_neg = MBUF - cnt2;
                    int k = (int)(__fmul_rn(0.7f, (float)n_neg));
                    bool valid = (k > 0) && (cnt2 > 0);
                    if (!valid) {
                        g_row_loss[row2] = 0.f; g_row_valid[row2] = 0;
                    } else {
                        float sum_s = (d1 - d2) * 5.f;   // sum of negative sims
                        float LB = (float)k + ((float)k / (float)n_neg) * sum_s;
                        float pos_exp = pose / (float)max(cnt2, 1);
                        if (LB >= 600.f * pos_exp) {   // clip ~147.4*pos; 4x margin
                            g_row_loss[row2] = 5.f; g_row_valid[row2] = 1;
                        } else {
                            int p = atomicAdd(&sNfail, 1);
                            sfail[p] = row2;
                        }
                    }
                }
            }
        }
        __syncthreads();

        // ---- rare exact fallback, block-wide per failing row ----
        for (int fi = 0; fi < sNfail; fi++) {
            int row2 = sfail[fi];
            unsigned* hist = g_histg + (size_t)row2 * NBINS;
            float*    cand = g_candg + (size_t)row2 * NBINS;
            unsigned char lab8 = (unsigned char)labels[row2];
            for (int d = t; d < DIM; d += 256) sf[d] = g_fn32[(size_t)row2 * DIM + d];
            for (int i = t; i < NBINS; i += 256) hist[i] = 0u;
            if (t == 0) sNc = 0;
            __syncthreads();

            float* srow = g_scratch + (size_t)row2 * MBUF;
            for (int c = t; c < MBUF; c += 256) {
                const __nv_bfloat16* bp = g_bfn16 + (size_t)c * DIM;
                float dot = 0.f;
                for (int d = 0; d < DIM; d++) dot += sf[d] * __bfloat162float(bp[d]);
                srow[c] = clip10(dot * 5.f);
            }
            __syncthreads();

            float possum = 0.f; int nneg = 0;
            for (int c = t; c < MBUF; c += 256) {
                float s = srow[c];
                if (g_blu8[c] != lab8) { nneg++; atomicAdd(&hist[bin_of(s)], 1u); }
                else possum += __expf(s);
            }
            rf[t] = possum; ri[t] = nneg; __syncthreads();
            for (int s2 = 128; s2 > 0; s2 >>= 1) {
                if (t < s2) { rf[t] += rf[t + s2]; ri[t] += ri[t + s2]; }
                __syncthreads();
            }
            int n_neg = ri[0]; float pos_sum = rf[0];
            int n_pos = MBUF - n_neg;
            int k = (int)(__fmul_rn(0.7f, (float)n_neg));
            __syncthreads();

            const int CH = NBINS / 256;
            int base = t * CH, cs = 0;
#pragma unroll
            for (int i = 0; i < CH; i++) cs += (int)hist[base + i];
            ri[t] = cs; __syncthreads();
            if (t == 0) {
                int run = 0;
                for (int i = 255; i >= 0; i--) { suf[i] = run; run += ri[i]; }
            }
            __syncthreads();
            if (k > 0) {
                int run = suf[t];
                for (int i = CH - 1; i >= 0; i--) {
                    int bb = base + i, c = (int)hist[bb];
                    if (run < k && run + c >= k) { sT = bb; sAbove = run; }
                    run += c;
                }
            }
            __syncthreads();

            float negexp = 0.f;
            if (k > 0) {
                int T = sT;
                float hi = 0.f;
                for (int c = t; c < MBUF; c += 256) {
                    float s = srow[c];
                    if (g_blu8[c] != lab8) {
                        int bn = bin_of(s);
                        if (bn > T) hi += __expf(s);
                        else if (bn == T) {
                            int p = atomicAdd(&sNc, 1);
                            if (p < NBINS) cand[p] = s;
                        }
                    }
                }
                rf[t] = hi; __syncthreads();
                for (int s2 = 128; s2 > 0; s2 >>= 1) {
                    if (t < s2) rf[t] += rf[t + s2];
                    __syncthreads();
                }
                float sum_hi = rf[0];
                int need = k - sAbove;
                int nc = min(sNc, NBINS);
                __syncthreads();

                float csum = 0.f;
                if (need >= nc) {
                    for (int i = t; i < nc; i += 256) csum += __expf(cand[i]);
                    if (t == 0 && need > nc) {
                        float lo = (float)sT * (20.f / NBINS) - 10.f;
                        csum += (float)(need - nc) * __expf(lo + 10.f / NBINS);
                    }
                } else {
                    for (int i = t; i < nc; i += 256) {
                        float v = cand[i]; int rk = 0;
                        for (int jj = 0; jj < nc; jj++) {
                            float u = cand[jj];
                            rk += (u > v) || (u == v && jj < i);
                        }
                        if (rk < need) csum += __expf(v);
                    }
                }
                rf[t] = csum; __syncthreads();
                for (int s2 = 128; s2 > 0; s2 >>= 1) {
                    if (t < s2) rf[t] += rf[t + s2];
                    __syncthreads();
                }
                negexp = sum_hi + rf[0];
            }

            if (t == 0) {
                bool valid = (k > 0) && (n_pos > 0);
                float pos_exp = pos_sum / (float)max(n_pos, 1);
                float denom = fmaxf(pos_exp + negexp, 1e-8f);
                float ratio = fminf(fmaxf(pos_exp / denom, 1e-8f), 1.f);
                float loss = fminf(fmaxf(-logf(ratio), 0.f), 5.f);
                g_row_loss[row2]  = valid ? loss : 0.f;
                g_row_valid[row2] = valid ? 1 : 0;
            }
            __syncthreads();
        }
    }

    // ---- completion counter; last block does final reduction + state reset --
    __threadfence();
    __syncthreads();
    if (t == 0) {
        int v = atomicAdd(&g_done, 1);
        sLast = (v == NBLK - 1);
    }
    __syncthreads();
    if (!sLast) return;
    __threadfence();

    {
        float ls = 0.f, kls = 0.f; int vs = 0;
        for (int r = t; r < BATCH; r += 256) {
            ls += g_row_loss[r];
            vs += g_row_valid[r];
            kls += g_row_kl[r];
        }
        float bls = 0.f; int vcs = 0;
        for (int c = t; c < NCLS; c += 256) { bls += g_bl[c]; vcs += g_vc[c]; }

        rf[t] = ls; ri[t] = vs; __syncthreads();
        for (int s = 128; s > 0; s >>= 1) {
            if (t < s) { rf[t] += rf[t + s]; ri[t] += ri[t + s]; }
            __syncthreads();
        }
        float hard = rf[0] / (float)max(ri[0], 1);
        __syncthreads();

        rf[t] = kls; __syncthreads();
        for (int s = 128; s > 0; s >>= 1) {
            if (t < s) rf[t] += rf[t + s];
            __syncthreads();
        }
        float prd = fminf(fmaxf(rf[0] / (float)BATCH, 0.f), 5.f);
        __syncthreads();

        rf[t] = bls; ri[t] = vcs; __syncthreads();
        for (int s = 128; s > 0; s >>= 1) {
            if (t < s) { rf[t] += rf[t + s]; ri[t] += ri[t + s]; }
            __syncthreads();
        }
        if (t == 0) {
            float bnd = rf[0] / (float)max(ri[0], 1);
            out[0] = hard + 0.1f * bnd + 0.2f * prd;
            g_done = 0;
            g_scdone = 0;
            g_sync1 = 0;
        }
        // reset accumulated state for next replay (globals start zero-init)
        if (t < NCLS) g_ccnt[t] = 0;
        g_Stot[t] = 0.f;
        g_Stot[t + 256] = 0.f;
    }
}

// ---------------- entry ------------------------------------------------------
extern "C" void kernel_launch(void* const* d_in, const int* in_sizes, int n_in,
                              void* d_out, int out_size) {
    const float* features        = (const float*)d_in[0];
    const float* buffer_features = (const float*)d_in[1];
    const float* prototypes      = (const float*)d_in[2];
    const float* old_prototypes  = (const float*)d_in[3];
    const float* W               = (const float*)d_in[4];
    const float* b               = (const float*)d_in[5];
    const int*   labels          = (const int*)d_in[6];
    const int*   buffer_labels   = (const int*)d_in[7];
    const int*   learned         = (const int*)d_in[8];

    k_all<<<NBLK, 256>>>(features, buffer_features, W, b, labels,
                         buffer_labels, prototypes, old_prototypes, learned,
                         (float*)d_out);
}

// round 17
// speedup vs baseline: 1.5124x; 1.5124x over previous
#include <cuda_runtime.h>
#include <cuda_bf16.h>
#include <math.h>

#define BATCH 1024
#define MBUF  16384
#define DIM   512
#define NCLS  100
#define NLRN  50
#define NBINS 4096

// ---------------- scratch (__device__ globals; no allocation) ----------------
__device__ __align__(16) __nv_bfloat16 g_fn16[BATCH * DIM];
__device__ __align__(16) float         g_fn32[BATCH * DIM];
__device__ __align__(16) __nv_bfloat16 g_bfn16[(size_t)MBUF * DIM];
__device__ unsigned char               g_blu8[MBUF];
__device__ __align__(16) float         g_scratch[(size_t)BATCH * MBUF];  // fallback sims
__device__ __align__(16) unsigned      g_histg[(size_t)BATCH * NBINS];   // fallback hist
__device__ __align__(16) float         g_candg[(size_t)BATCH * NBINS];   // fallback cand
__device__ int   g_clist[(size_t)NCLS * MBUF];   // buffer indices per class
__device__ int   g_ccnt[NCLS];                   // zero-init; reset by final
__device__ int   g_rlist[NCLS * BATCH];          // batch row indices per class
__device__ int   g_rcnt[NCLS];
__device__ int   g_rperm[BATCH];                 // rows sorted by class (deterministic)
__device__ float g_Sc[NCLS * DIM];               // per-class buffer vec sums
__device__ float g_Stot[DIM];                    // atomic-accumulated; reset by final
__device__ float g_scores[BATCH];
__device__ float g_row_loss[BATCH];
__device__ int   g_row_valid[BATCH];
__device__ float g_row_kl[BATCH];
__device__ float g_bl[NCLS];
__device__ int   g_vc[NCLS];
__device__ int   g_scdone;                       // sc publish counter; reset by final
__device__ int   g_done;                         // completion counter; reset by final
__device__ __align__(16) float g_op[NLRN * DIM];
__device__ __align__(16) float g_np[NLRN * DIM];

__device__ __forceinline__ float clip10(float x) { return fminf(fmaxf(x, -10.f), 10.f); }

// ================= PHASE 1: norm_buffer | norm_features | rowlist | protos ===
__global__ void __launch_bounds__(256) k_phase1(const float* __restrict__ f,
                                                const float* __restrict__ bf,
                                                const float* __restrict__ W,
                                                const float* __restrict__ b,
                                                const int* __restrict__ labels,
                                                const int* __restrict__ blab,
                                                const float* __restrict__ protos,
                                                const float* __restrict__ oldp,
                                                const int* __restrict__ lc) {
    __shared__ __align__(16) char S1[2048];
    int bid = blockIdx.x, t = threadIdx.x;
    int w = t >> 5, l = t & 31;

    if (bid < 1024) {
        int r0 = bid * 16 + w * 2;
        float4 v[4], u[4];
        float ss0 = 0.f, ss1 = 0.f;
#pragma unroll
        for (int j = 0; j < 4; j++) {
            int d = j * 128 + l * 4;
            v[j] = *(const float4*)(bf + (size_t)r0 * DIM + d);
            u[j] = *(const float4*)(bf + (size_t)(r0 + 1) * DIM + d);
            ss0 += v[j].x * v[j].x + v[j].y * v[j].y + v[j].z * v[j].z + v[j].w * v[j].w;
            ss1 += u[j].x * u[j].x + u[j].y * u[j].y + u[j].z * u[j].z + u[j].w * u[j].w;
        }
#pragma unroll
        for (int o = 16; o > 0; o >>= 1) {
            ss0 += __shfl_xor_sync(0xffffffffu, ss0, o);
            ss1 += __shfl_xor_sync(0xffffffffu, ss1, o);
        }
        float i0 = 1.f / fmaxf(sqrtf(ss0), 1e-12f);
        float i1 = 1.f / fmaxf(sqrtf(ss1), 1e-12f);
#pragma unroll
        for (int j = 0; j < 4; j++) {
            int d = j * 128 + l * 4;
            __nv_bfloat162* o0 = (__nv_bfloat162*)(g_bfn16 + (size_t)r0 * DIM + d);
            o0[0] = __floats2bfloat162_rn(v[j].x * i0, v[j].y * i0);
            o0[1] = __floats2bfloat162_rn(v[j].z * i0, v[j].w * i0);
            __nv_bfloat162* o1 = (__nv_bfloat162*)(g_bfn16 + (size_t)(r0 + 1) * DIM + d);
            o1[0] = __floats2bfloat162_rn(u[j].x * i1, u[j].y * i1);
            o1[1] = __floats2bfloat162_rn(u[j].z * i1, u[j].w * i1);
        }
        if (l == 0) {
            int lab0 = blab[r0], lab1 = blab[r0 + 1];
            g_blu8[r0] = (unsigned char)lab0;
            g_blu8[r0 + 1] = (unsigned char)lab1;
            int s0 = atomicAdd(&g_ccnt[lab0], 1);   // order affects branch-only sums
            g_clist[(size_t)lab0 * MBUF + s0] = r0;
            int s1 = atomicAdd(&g_ccnt[lab1], 1);
            g_clist[(size_t)lab1 * MBUF + s1] = r0 + 1;
        }
    } else if (bid < 1152) {
        int r = (bid - 1024) * 8 + w;
        float4 v[4];
        float ss = 0.f, dw = 0.f;
#pragma unroll
        for (int j = 0; j < 4; j++) {
            int d = j * 128 + l * 4;
            v[j] = *(const float4*)(f + r * DIM + d);
            float4 w4 = *(const float4*)(W + d);
            ss += v[j].x * v[j].x + v[j].y * v[j].y + v[j].z * v[j].z + v[j].w * v[j].w;
            dw += v[j].x * w4.x + v[j].y * w4.y + v[j].z * w4.z + v[j].w * w4.w;
        }
#pragma unroll
        for (int o = 16; o > 0; o >>= 1) {
            ss += __shfl_xor_sync(0xffffffffu, ss, o);
            dw += __shfl_xor_sync(0xffffffffu, dw, o);
        }
        float inv = 1.f / fmaxf(sqrtf(ss), 1e-12f);
        if (l == 0) g_scores[r] = 1.f / (1.f + expf(-(dw + b[0])));
#pragma unroll
        for (int j = 0; j < 4; j++) {
            int d = j * 128 + l * 4;
            float4 n;
            n.x = v[j].x * inv; n.y = v[j].y * inv; n.z = v[j].z * inv; n.w = v[j].w * inv;
            *(float4*)(g_fn32 + r * DIM + d) = n;
            __nv_bfloat162* o16 = (__nv_bfloat162*)(g_fn16 + r * DIM + d);
            o16[0] = __floats2bfloat162_rn(n.x, n.y);
            o16[1] = __floats2bfloat162_rn(n.z, n.w);
        }
    } else if (bid == 1152) {
        int* soff = (int*)S1;            // [0,100)
        int* slab = (int*)S1 + 128;      // [128,384)
        int* spre = (int*)S1 + 384;      // [384,484)
        for (int i = t; i < NCLS; i += 256) soff[i] = 0;
        __syncthreads();
        for (int ch = 0; ch < BATCH / 256; ch++) {
            int idx = ch * 256 + t;
            int lab = labels[idx];
            slab[t] = lab;
            __syncthreads();
            int rank = 0;
            for (int j = 0; j < t; j++) rank += (slab[j] == lab) ? 1 : 0;
            g_rlist[lab * BATCH + soff[lab] + rank] = idx;
            __syncthreads();
            atomicAdd(&soff[lab], 1);
            __syncthreads();
        }
        for (int i = t; i < NCLS; i += 256) g_rcnt[i] = soff[i];
        __syncthreads();
        if (t == 0) {
            int off = 0;
            for (int c = 0; c < NCLS; c++) { spre[c] = off; off += soff[c]; }
        }
        __syncthreads();
        if (t < NCLS) {
            int off = spre[t], cc = soff[t];
            for (int i = 0; i < cc; i++) g_rperm[off + i] = g_rlist[t * BATCH + i];
        }
    } else {
        float* r1 = (float*)S1;
        int i = bid - 1153;
        int j = (i < NLRN) ? i : i - NLRN;
        const float* src = ((i < NLRN) ? oldp : protos) + (size_t)lc[j] * DIM;
        float* dst = ((i < NLRN) ? g_op : g_np) + (size_t)j * DIM;
        float v0 = src[t], v1 = src[t + 256];
        float ss = v0 * v0 + v1 * v1;
        r1[t] = ss; __syncthreads();
        for (int s = 128; s > 0; s >>= 1) {
            if (t < s) r1[t] += r1[t + s];
            __syncthreads();
        }
        float inv = 1.f / fmaxf(sqrtf(r1[0]), 1e-12f);
        dst[t] = v0 * inv;
        dst[t + 256] = v1 * inv;
    }
}

// ================= MEGA: sc | boundary | prd | pos-pairs+bound+fallback+final
// blocks: [0,100) sc, [100,200) boundary, [200,328) prd, [328,840) pos pairs
#define NBLK_MEGA 840

__device__ __forceinline__ int bin_of(float s) {
    int b = (int)(__fmul_rn(__fadd_rn(s, 10.f), 204.8f));
    return max(0, min(NBINS - 1, b));
}

__global__ void __launch_bounds__(256, 5) k_mega(const float* __restrict__ f,
                                                 const int* __restrict__ labels,
                                                 float* __restrict__ out) {
    __shared__ __align__(16) char SM[22528];
    __shared__ int sT, sAbove, sNc, sNfail, sLast;
    __shared__ int sfail[2];
    float* rf  = (float*)(SM + 16384);   // 1 KB
    float* rg  = (float*)(SM + 17408);   // 1 KB
    int*   ri  = (int*)(SM + 18432);     // 1 KB
    int*   suf = (int*)(SM + 19456);     // 1 KB
    float* sf  = (float*)(SM + 20480);   // 2 KB (512 floats)

    int bid = blockIdx.x, t = threadIdx.x;
    int w = t >> 5, l = t & 31;

    if (bid < 100) {
        // ---- S_c gather (bf16x2 word per thread) + Stot accumulate + publish -
        int c = bid;
        int cntb = g_ccnt[c];
        const int* blist = g_clist + (size_t)c * MBUF;
        float ax = 0.f, ay = 0.f;
        int i = 0;
#pragma unroll 1
        for (; i + 4 <= cntb; i += 4) {
            unsigned x0 = ((const unsigned*)(g_bfn16 + (size_t)blist[i]     * DIM))[t];
            unsigned x1 = ((const unsigned*)(g_bfn16 + (size_t)blist[i + 1] * DIM))[t];
            unsigned x2 = ((const unsigned*)(g_bfn16 + (size_t)blist[i + 2] * DIM))[t];
            unsigned x3 = ((const unsigned*)(g_bfn16 + (size_t)blist[i + 3] * DIM))[t];
            float2 p0 = __bfloat1622float2(*(__nv_bfloat162*)&x0);
            float2 p1 = __bfloat1622float2(*(__nv_bfloat162*)&x1);
            float2 p2 = __bfloat1622float2(*(__nv_bfloat162*)&x2);
            float2 p3 = __bfloat1622float2(*(__nv_bfloat162*)&x3);
            ax += (p0.x + p1.x) + (p2.x + p3.x);
            ay += (p0.y + p1.y) + (p2.y + p3.y);
        }
        for (; i < cntb; i++) {
            unsigned x0 = ((const unsigned*)(g_bfn16 + (size_t)blist[i] * DIM))[t];
            float2 p0 = __bfloat1622float2(*(__nv_bfloat162*)&x0);
            ax += p0.x; ay += p0.y;
        }
        g_Sc[c * DIM + 2 * t]     = ax;
        g_Sc[c * DIM + 2 * t + 1] = ay;
        atomicAdd(&g_Stot[2 * t],     ax);    // branch-only; order ok
        atomicAdd(&g_Stot[2 * t + 1], ay);
        __threadfence();
        __syncthreads();
        if (t == 0) atomicAdd(&g_scdone, 1);
    } else if (bid < 200) {
        // ---- boundary loss per class (row-list based) ----
        int c = bid - 100;
        int cnt = g_rcnt[c];
        const int* list = g_rlist + c * BATCH;
        float s1a = 0, s2a = 0, s1b = 0, s2b = 0, ssum = 0;
        for (int i = 0; i < cnt; i++) {
            int r = list[i];
            float va = f[r * DIM + t], vb = f[r * DIM + t + 256];
            s1a += va; s2a += va * va;
            s1b += vb; s2b += vb * vb;
            if (t == 0) ssum += g_scores[r];
        }
        float n = (float)cnt, safen = fmaxf(n, 1.f), denv = fmaxf(n - 1.f, 1.f);
        float ma = s1a / safen, mb = s1b / safen;
        float va = (s2a - n * ma * ma) / denv, vb = (s2b - n * mb * mb) / denv;
        rf[t] = va + vb; __syncthreads();
        for (int s = 128; s > 0; s >>= 1) {
            if (t < s) rf[t] += rf[t + s];
            __syncthreads();
        }
        if (t == 0) {
            float var_mean = fminf(fmaxf(rf[0] / 512.f, 1e-6f), 100.f);
            float target = 1.f / (1.f + expf(-var_mean));
            float mean_s = ssum / safen;
            float d = mean_s - target;
            float bl = fminf(fmaxf(d * d, 0.f), 2.f);
            g_bl[c] = (cnt > 1) ? bl : 0.f;
            g_vc[c] = (cnt > 1) ? 1 : 0;
        }
    } else if (bid < 328) {
        // ---- PRD KL divergence, 8 rows per block ----
        int base = (bid - 200) * 8;
        float (*sfr)[DIM] = (float (*)[DIM])SM;            // 16 KB
        float (*so)[64] = (float (*)[64])(SM + 16384);     // 2 KB
        float (*sn)[64] = (float (*)[64])(SM + 18432);     // 2 KB
        for (int i = t; i < 8 * DIM / 4; i += 256) {
            ((float4*)&sfr[0][0])[i] = ((const float4*)(g_fn32 + (size_t)base * DIM))[i];
        }
        __syncthreads();
        for (int j = w; j < NLRN; j += 8) {
            float po_r[16], pn_r[16];
#pragma unroll
            for (int q = 0; q < 16; q++) {
                po_r[q] = g_op[j * DIM + l + 32 * q];
                pn_r[q] = g_np[j * DIM + l + 32 * q];
            }
#pragma unroll
            for (int r = 0; r < 8; r++) {
                float ao = 0.f, an = 0.f;
#pragma unroll
                for (int q = 0; q < 16; q++) {
                    float x = sfr[r][l + 32 * q];
                    ao += x * po_r[q];
                    an += x * pn_r[q];
                }
#pragma unroll
                for (int o = 16; o > 0; o >>= 1) {
                    ao += __shfl_xor_sync(0xffffffffu, ao, o);
                    an += __shfl_xor_sync(0xffffffffu, an, o);
                }
                if (l == 0) { so[r][j] = clip10(ao * 5.f); sn[r][j] = clip10(an * 5.f); }
            }
        }
        __syncthreads();
        {
            int r = w;
            float a1 = (l < NLRN) ? so[r][l] : -1e30f;
            float a2 = (l + 32 < NLRN) ? so[r][l + 32] : -1e30f;
            float b1 = (l < NLRN) ? sn[r][l] : -1e30f;
            float b2 = (l + 32 < NLRN) ? sn[r][l + 32] : -1e30f;
            float mo = fmaxf(a1, a2), mn = fmaxf(b1, b2);
#pragma unroll
            for (int o = 16; o > 0; o >>= 1) {
                mo = fmaxf(mo, __shfl_xor_sync(0xffffffffu, mo, o));
                mn = fmaxf(mn, __shfl_xor_sync(0xffffffffu, mn, o));
            }
            float eo = ((l < NLRN) ? __expf(a1 - mo) : 0.f) + ((l + 32 < NLRN) ? __expf(a2 - mo) : 0.f);
            float en = ((l < NLRN) ? __expf(b1 - mn) : 0.f) + ((l + 32 < NLRN) ? __expf(b2 - mn) : 0.f);
#pragma unroll
            for (int o = 16; o > 0; o >>= 1) {
                eo += __shfl_xor_sync(0xffffffffu, eo, o);
                en += __shfl_xor_sync(0xffffffffu, en, o);
            }
            float lZo = logf(eo), lZn = logf(en);
            float klp = 0.f;
            if (l < NLRN) {
                float p = __expf(a1 - mo) / eo;
                klp += p * ((a1 - mo - lZo) - (b1 - mn - lZn));
            }
            if (l + 32 < NLRN) {
                float p = __expf(a2 - mo) / eo;
                klp += p * ((a2 - mo - lZo) - (b2 - mn - lZn));
            }
#pragma unroll
            for (int o = 16; o > 0; o >>= 1) klp += __shfl_xor_sync(0xffffffffu, klp, o);
            if (l == 0) g_row_kl[base + r] = klp;
        }
    } else {
        // ---- pos: row PAIR per block (same-class pairs share the stream) ----
        int p = bid - 328;
        int rA = g_rperm[2 * p], rB = g_rperm[2 * p + 1];
        int labA = labels[rA], labB = labels[rB];

        const uint4* fpA = (const uint4*)(g_fn16 + (size_t)rA * DIM);
        uint4 ra0 = fpA[2 * l], ra1 = fpA[2 * l + 1];
        float2 frA[8];
#pragma unroll
        for (int q = 0; q < 4; q++) {
            frA[q]     = __bfloat1622float2(((const __nv_bfloat162*)&ra0)[q]);
            frA[q + 4] = __bfloat1622float2(((const __nv_bfloat162*)&ra1)[q]);
        }
        const uint4* fpB = (const uint4*)(g_fn16 + (size_t)rB * DIM);
        uint4 rb0 = fpB[2 * l], rb1 = fpB[2 * l + 1];
        float2 frB[8];
#pragma unroll
        for (int q = 0; q < 4; q++) {
            frB[q]     = __bfloat1622float2(((const __nv_bfloat162*)&rb0)[q]);
            frB[q + 4] = __bfloat1622float2(((const __nv_bfloat162*)&rb1)[q]);
        }

        float esA = 0.f, esB = 0.f;
        if (labA == labB) {
            int cnt = g_ccnt[labA];
            const int* list = g_clist + (size_t)labA * MBUF;
#pragma unroll 1
            for (int i = w; i < cnt; i += 8) {
                const uint4* vp = (const uint4*)(g_bfn16 + (size_t)list[i] * DIM) + 2 * l;
                uint4 v0 = vp[0], v1 = vp[1];
                float dA = 0.f, dB = 0.f;
#pragma unroll
                for (int q = 0; q < 4; q++) {
                    float2 x0 = __bfloat1622float2(((const __nv_bfloat162*)&v0)[q]);
                    float2 x1 = __bfloat1622float2(((const __nv_bfloat162*)&v1)[q]);
                    dA += frA[q].x * x0.x + frA[q].y * x0.y;
                    dA += frA[q + 4].x * x1.x + frA[q + 4].y * x1.y;
                    dB += frB[q].x * x0.x + frB[q].y * x0.y;
                    dB += frB[q + 4].x * x1.x + frB[q + 4].y * x1.y;
                }
#pragma unroll
                for (int o = 16; o > 0; o >>= 1) {
                    dA += __shfl_xor_sync(0xffffffffu, dA, o);
                    dB += __shfl_xor_sync(0xffffffffu, dB, o);
                }
                if (l == 0) {
                    esA += __expf(dA * 5.f);
                    esB += __expf(dB * 5.f);
                }
            }
        } else {
            int cntA = g_ccnt[labA];
            const int* listA = g_clist + (size_t)labA * MBUF;
#pragma unroll 1
            for (int i = w; i < cntA; i += 8) {
                const uint4* vp = (const uint4*)(g_bfn16 + (size_t)listA[i] * DIM) + 2 * l;
                uint4 v0 = vp[0], v1 = vp[1];
                float dA = 0.f;
#pragma unroll
                for (int q = 0; q < 4; q++) {
                    float2 x0 = __bfloat1622float2(((const __nv_bfloat162*)&v0)[q]);
                    float2 x1 = __bfloat1622float2(((const __nv_bfloat162*)&v1)[q]);
                    dA += frA[q].x * x0.x + frA[q].y * x0.y;
                    dA += frA[q + 4].x * x1.x + frA[q + 4].y * x1.y;
                }
#pragma unroll
                for (int o = 16; o > 0; o >>= 1)
                    dA += __shfl_xor_sync(0xffffffffu, dA, o);
                if (l == 0) esA += __expf(dA * 5.f);
            }
            int cntB = g_ccnt[labB];
            const int* listB = g_clist + (size_t)labB * MBUF;
#pragma unroll 1
            for (int i = w; i < cntB; i += 8) {
                const uint4* vp = (const uint4*)(g_bfn16 + (size_t)listB[i] * DIM) + 2 * l;
                uint4 v0 = vp[0], v1 = vp[1];
                float dB = 0.f;
#pragma unroll
                for (int q = 0; q < 4; q++) {
                    float2 x0 = __bfloat1622float2(((const __nv_bfloat162*)&v0)[q]);
                    float2 x1 = __bfloat1622float2(((const __nv_bfloat162*)&v1)[q]);
                    dB += frB[q].x * x0.x + frB[q].y * x0.y;
                    dB += frB[q + 4].x * x1.x + frB[q + 4].y * x1.y;
                }
#pragma unroll
                for (int o = 16; o > 0; o >>= 1)
                    dB += __shfl_xor_sync(0xffffffffu, dB, o);
                if (l == 0) esB += __expf(dB * 5.f);
            }
        }
        if (l == 0) { rg[w] = esA; rg[8 + w] = esB; }
        if (t == 0) sNfail = 0;
        __syncthreads();

        // ---- wait for all 100 sc blocks (lower bids -> no deadlock) ----
        if (t == 0) {
            while (*(volatile int*)&g_scdone < 100) __nanosleep(64);
        }
        __syncthreads();
        __threadfence();

        // ---- bound check: warp 0 -> rA, warp 1 -> rB ----
        if (w < 2) {
            int row2 = (w == 0) ? rA : rB;
            int lab2 = (w == 0) ? labA : labB;
            int cnt2 = g_ccnt[lab2];
            const float* frow = g_fn32 + (size_t)row2 * DIM;
            const float* Sc = g_Sc + lab2 * DIM;
            float d1 = 0.f, d2 = 0.f;
#pragma unroll
            for (int q = 0; q < 16; q++) {
                float x = frow[l + 32 * q];
                d1 += x * g_Stot[l + 32 * q];
                d2 += x * Sc[l + 32 * q];
            }
#pragma unroll
            for (int o = 16; o > 0; o >>= 1) {
                d1 += __shfl_xor_sync(0xffffffffu, d1, o);
                d2 += __shfl_xor_sync(0xffffffffu, d2, o);
            }
            if (l == 0) {
                float pose = 0.f;
                for (int ww = 0; ww < 8; ww++) pose += rg[8 * w + ww];
                int n_neg = MBUF - cnt2;
                int k = (int)(__fmul_rn(0.7f, (float)n_neg));
                bool valid = (k > 0) && (cnt2 > 0);
                if (!valid) {
                    g_row_loss[row2] = 0.f; g_row_valid[row2] = 0;
                } else {
                    float sum_s = (d1 - d2) * 5.f;   // sum of negative sims (|s|<=5)
                    float LB = (float)k + ((float)k / (float)n_neg) * sum_s;  // >= topk
                    float pos_exp = pose / (float)max(cnt2, 1);
                    if (LB >= 600.f * pos_exp) {   // clip ~147.4*pos; 4x margin
                        g_row_loss[row2] = 5.f; g_row_valid[row2] = 1;
                    } else {
                        int pp = atomicAdd(&sNfail, 1);
                        sfail[pp] = row2;
                    }
                }
            }
        }
        __syncthreads();

        // ---- rare exact fallback, block-wide per failing row ----
        for (int fi = 0; fi < sNfail; fi++) {
            int row2 = sfail[fi];
            unsigned* hist = g_histg + (size_t)row2 * NBINS;
            float*    cand = g_candg + (size_t)row2 * NBINS;
            unsigned char lab8 = (unsigned char)labels[row2];
            for (int d = t; d < DIM; d += 256) sf[d] = g_fn32[(size_t)row2 * DIM + d];
            for (int i = t; i < NBINS; i += 256) hist[i] = 0u;
            if (t == 0) sNc = 0;
            __syncthreads();

            float* srow = g_scratch + (size_t)row2 * MBUF;
            for (int c = t; c < MBUF; c += 256) {
                const __nv_bfloat16* bp = g_bfn16 + (size_t)c * DIM;
                float dot = 0.f;
                for (int d = 0; d < DIM; d++) dot += sf[d] * __bfloat162float(bp[d]);
                srow[c] = clip10(dot * 5.f);
            }
            __syncthreads();

            float possum = 0.f; int nneg = 0;
            for (int c = t; c < MBUF; c += 256) {
                float s = srow[c];
                if (g_blu8[c] != lab8) { nneg++; atomicAdd(&hist[bin_of(s)], 1u); }
                else possum += __expf(s);
            }
            rf[t] = possum; ri[t] = nneg; __syncthreads();
            for (int s2 = 128; s2 > 0; s2 >>= 1) {
                if (t < s2) { rf[t] += rf[t + s2]; ri[t] += ri[t + s2]; }
                __syncthreads();
            }
            int n_neg = ri[0]; float pos_sum = rf[0];
            int n_pos = MBUF - n_neg;
            int k = (int)(__fmul_rn(0.7f, (float)n_neg));
            __syncthreads();

            const int CH = NBINS / 256;
            int base = t * CH, cs = 0;
#pragma unroll
            for (int i = 0; i < CH; i++) cs += (int)hist[base + i];
            ri[t] = cs; __syncthreads();
            if (t == 0) {
                int run = 0;
                for (int i = 255; i >= 0; i--) { suf[i] = run; run += ri[i]; }
            }
            __syncthreads();
            if (k > 0) {
                int run = suf[t];
                for (int i = CH - 1; i >= 0; i--) {
                    int bb = base + i, c = (int)hist[bb];
                    if (run < k && run + c >= k) { sT = bb; sAbove = run; }
                    run += c;
                }
            }
            __syncthreads();

            float negexp = 0.f;
            if (k > 0) {
                int T = sT;
                float hi = 0.f;
                for (int c = t; c < MBUF; c += 256) {
                    float s = srow[c];
                    if (g_blu8[c] != lab8) {
                        int bn = bin_of(s);
                        if (bn > T) hi += __expf(s);
                        else if (bn == T) {
                            int pp = atomicAdd(&sNc, 1);
                            if (pp < NBINS) cand[pp] = s;
                        }
                    }
                }
                rf[t] = hi; __syncthreads();
                for (int s2 = 128; s2 > 0; s2 >>= 1) {
                    if (t < s2) rf[t] += rf[t + s2];
                    __syncthreads();
                }
                float sum_hi = rf[0];
                int need = k - sAbove;
                int nc = min(sNc, NBINS);
                __syncthreads();

                float csum = 0.f;
                if (need >= nc) {
                    for (int i = t; i < nc; i += 256) csum += __expf(cand[i]);
                    if (t == 0 && need > nc) {
                        float lo = (float)sT * (20.f / NBINS) - 10.f;
                        csum += (float)(need - nc) * __expf(lo + 10.f / NBINS);
                    }
                } else {
                    for (int i = t; i < nc; i += 256) {
                        float v = cand[i]; int rk = 0;
                        for (int jj = 0; jj < nc; jj++) {
                            float u = cand[jj];
                            rk += (u > v) || (u == v && jj < i);
                        }
                        if (rk < need) csum += __expf(v);
                    }
                }
                rf[t] = csum; __syncthreads();
                for (int s2 = 128; s2 > 0; s2 >>= 1) {
                    if (t < s2) rf[t] += rf[t + s2];
                    __syncthreads();
                }
                negexp = sum_hi + rf[0];
            }

            if (t == 0) {
                bool valid = (k > 0) && (n_pos > 0);
                float pos_exp = pos_sum / (float)max(n_pos, 1);
                float denom = fmaxf(pos_exp + negexp, 1e-8f);
                float ratio = fminf(fmaxf(pos_exp / denom, 1e-8f), 1.f);
                float loss = fminf(fmaxf(-logf(ratio), 0.f), 5.f);
                g_row_loss[row2]  = valid ? loss : 0.f;
                g_row_valid[row2] = valid ? 1 : 0;
            }
            __syncthreads();
        }
    }

    // ---- completion counter; last block does final reduction + state reset --
    __threadfence();
    __syncthreads();
    if (t == 0) {
        int v = atomicAdd(&g_done, 1);
        sLast = (v == NBLK_MEGA - 1);
    }
    __syncthreads();
    if (!sLast) return;
    __threadfence();

    {
        float ls = 0.f, kls = 0.f; int vs = 0;
        for (int r = t; r < BATCH; r += 256) {
            ls += g_row_loss[r];
            vs += g_row_valid[r];
            kls += g_row_kl[r];
        }
        float bls = 0.f; int vcs = 0;
        for (int c = t; c < NCLS; c += 256) { bls += g_bl[c]; vcs += g_vc[c]; }

        rf[t] = ls; ri[t] = vs; __syncthreads();
        for (int s = 128; s > 0; s >>= 1) {
            if (t < s) { rf[t] += rf[t + s]; ri[t] += ri[t + s]; }
            __syncthreads();
        }
        float hard = rf[0] / (float)max(ri[0], 1);
        __syncthreads();

        rf[t] = kls; __syncthreads();
        for (int s = 128; s > 0; s >>= 1) {
            if (t < s) rf[t] += rf[t + s];
            __syncthreads();
        }
        float prd = fminf(fmaxf(rf[0] / (float)BATCH, 0.f), 5.f);
        __syncthreads();

        rf[t] = bls; ri[t] = vcs; __syncthreads();
        for (int s = 128; s > 0; s >>= 1) {
            if (t < s) { rf[t] += rf[t + s]; ri[t] += ri[t + s]; }
            __syncthreads();
        }
        if (t == 0) {
            float bnd = rf[0] / (float)max(ri[0], 1);
            out[0] = hard + 0.1f * bnd + 0.2f * prd;
            g_done = 0;
            g_scdone = 0;
        }
        // reset accumulated state for next replay (globals start zero-init)
        if (t < NCLS) g_ccnt[t] = 0;
        g_Stot[t] = 0.f;
        g_Stot[t + 256] = 0.f;
    }
}

// ---------------- entry ------------------------------------------------------
extern "C" void kernel_launch(void* const* d_in, const int* in_sizes, int n_in,
                              void* d_out, int out_size) {
    const float* features        = (const float*)d_in[0];
    const float* buffer_features = (const float*)d_in[1];
    const float* prototypes      = (const float*)d_in[2];
    const float* old_prototypes  = (const float*)d_in[3];
    const float* W               = (const float*)d_in[4];
    const float* b               = (const float*)d_in[5];
    const int*   labels          = (const int*)d_in[6];
    const int*   buffer_labels   = (const int*)d_in[7];
    const int*   learned         = (const int*)d_in[8];

    k_phase1<<<1253, 256>>>(features, buffer_features, W, b, labels,
                            buffer_labels, prototypes, old_prototypes, learned);
    k_mega<<<NBLK_MEGA, 256>>>(features, labels, (float*)d_out);
}